// round 6
// baseline (speedup 1.0000x reference)
#include <cuda_runtime.h>
#include <cuda_bf16.h>

// ---------------------------------------------------------------------------
// ENAS RNN — round 6: occupancy + ILP rework.
//   n-tile 8 per matrix (2x CTAs), per-term accumulators (3x MMA ILP),
//   S=6 cp.async pipeline, one barrier per chunk, no bounds checks.
// mma.sync bf16 3-term split (hi*hi + hi*lo + lo*hi), fp32 accum.
// ---------------------------------------------------------------------------

namespace {

typedef unsigned int u32;
typedef __nv_bfloat16 bf16;

constexpr int Hd = 1000;
constexpr int Bb = 64;
constexpr int Tt = 64;
constexpr int Vv = 10000;

constexpr int KP = 1024;          // padded K pitch (elements)
constexpr int S = 6;              // pipeline stages
constexpr int KC = 32;            // k per chunk
constexpr int NCHUNK = KP / KC;   // 32

// ---------------- static device storage (zero-initialized at load) ---------
__device__ bf16 g_Whhi[11 * 1000 * KP], g_Whlo[11 * 1000 * KP];
__device__ bf16 g_Wchi[11 * 1000 * KP], g_Wclo[11 * 1000 * KP];
__device__ bf16 g_dechi[10000 * KP], g_declo[10000 * KP];
__device__ bf16 g_embhi[10000 * KP], g_emblo[10000 * KP];
__device__ bf16 g_wxhe_hi[1000 * KP], g_wxhe_lo[1000 * KP];
__device__ bf16 g_wxhh_hi[1000 * KP], g_wxhh_lo[1000 * KP];
__device__ bf16 g_wxce_hi[1000 * KP], g_wxce_lo[1000 * KP];
__device__ bf16 g_wxch_hi[1000 * KP], g_wxch_lo[1000 * KP];

__device__ float g_h[12][Bb * Hd];
__device__ bf16  g_hhi[12][Bb * KP];
__device__ bf16  g_hlo[12][Bb * KP];
__device__ float g_c0[Bb * Hd];
__device__ float g_Ph[Tt * Bb * Hd];
__device__ float g_Pc[Tt * Bb * Hd];
__device__ bf16  g_outshi[Tt * Bb * KP];
__device__ bf16  g_outslo[Tt * Bb * KP];

// ---------------- helpers ---------------------------------------------------
__device__ __forceinline__ float sigmf(float x) { return 1.0f / (1.0f + expf(-x)); }

__device__ __forceinline__ float applyAct(int a, float v) {
    switch (a) {
        case 0: return fmaxf(v, 0.0f);
        case 1: return tanhf(v);
        case 2: return sigmf(v);
        default: return v;
    }
}

__device__ __forceinline__ void split1(float x, bf16& h, bf16& l) {
    h = __float2bfloat16(x);
    l = __float2bfloat16(x - __bfloat162float(h));
}
__device__ __forceinline__ u32 b2u(bf16 a, bf16 b) {
    return (u32)__bfloat16_as_ushort(a) | ((u32)__bfloat16_as_ushort(b) << 16);
}

__device__ __forceinline__ void mma16816(float (&d)[4], const u32 (&a)[4], u32 b0, u32 b1) {
    asm volatile(
        "mma.sync.aligned.m16n8k16.row.col.f32.bf16.bf16.f32 "
        "{%0,%1,%2,%3}, {%4,%5,%6,%7}, {%8,%9}, {%0,%1,%2,%3};"
        : "+f"(d[0]), "+f"(d[1]), "+f"(d[2]), "+f"(d[3])
        : "r"(a[0]), "r"(a[1]), "r"(a[2]), "r"(a[3]), "r"(b0), "r"(b1));
}
__device__ __forceinline__ void ldmA(u32 a, u32 (&r)[4]) {
    asm volatile("ldmatrix.sync.aligned.m8n8.x4.shared.b16 {%0,%1,%2,%3}, [%4];"
                 : "=r"(r[0]), "=r"(r[1]), "=r"(r[2]), "=r"(r[3]) : "r"(a));
}
__device__ __forceinline__ void ldmB(u32 a, u32& b0, u32& b1) {
    asm volatile("ldmatrix.sync.aligned.m8n8.x2.shared.b16 {%0,%1}, [%2];"
                 : "=r"(b0), "=r"(b1) : "r"(a));
}
__device__ __forceinline__ void cpa16(u32 dst, const void* src) {
    asm volatile("cp.async.cg.shared.global [%0], [%1], 16;" :: "r"(dst), "l"(src));
}
__device__ __forceinline__ void cp_commit() { asm volatile("cp.async.commit_group;"); }

struct BPtr { const bf16* hi; const bf16* lo; };
struct EdgeDesc { int parent; int child; int w; int act; int split; };
struct LevelDesc { EdgeDesc e[3]; };

// ---------------------------------------------------------------------------
// Pipelined GEMM mainloop. A: 64 x KP bf16 hi/lo (row via arow).
// B: NB groups of 8 rows (bsrc maps group-row 0..NB*8-1 to hi/lo row ptrs).
// 128 threads = 4 warps; warp w owns m [16w, 16w+16).
// acc[j][t] : group j, split-term t (0: Ahi*Bhi, 1: Ahi*Blo, 2: Alo*Bhi) —
// separate accumulators per term to break HMMA RAW chains; summed at epilogue.
//
// Invariant: entering iteration ch, committed groups = ch + (S-1) (empty
// commits at the tail), so wait_group(S-2) proves chunk ch complete.
// Single barrier per chunk: the top sync of iter ch proves all warps are done
// reading stage (ch-1)%S, the only stage the iter-ch prefetch overwrites.
// ---------------------------------------------------------------------------
template <int NB, class AROW, class BSRC>
__device__ __forceinline__ void run_pipeline(
    char* smem, const bf16* __restrict__ Ah, const bf16* __restrict__ Al,
    AROW arow, BSRC bsrc, float (&acc)[NB][3][4])
{
    constexpr int AHI = 0, ALO = 5120, BHI = 10240, BLO = 10240 + NB * 640;
    constexpr int SS = 10240 + 2 * NB * 640;
    constexpr int BV = NB * 32;          // 16B vectors per precision
    constexpr int BITER = (2 * BV) / 128;

    const int tid = threadIdx.x;
    const u32 sbase = (u32)__cvta_generic_to_shared(smem);

    // A: 64 rows x 32 bf16 per chunk; 4 threads/row; two row-sets per thread.
    const size_t aoff0 = (size_t)arow(tid >> 2) * KP + (tid & 3) * 8;
    const size_t aoff1 = (size_t)arow((tid + 128) >> 2) * KP + (tid & 3) * 8;
    const u32 adst0 = (u32)((tid >> 2) * 80 + (tid & 3) * 16);
    const u32 adst1 = (u32)(((tid + 128) >> 2) * 80 + (tid & 3) * 16);

    const bf16* bp[BITER];
    u32 bd[BITER];
#pragma unroll
    for (int i = 0; i < BITER; i++) {
        int e = tid + i * 128;
        int lo = (e >= BV);
        int f = lo ? e - BV : e;
        BPtr p = bsrc(f >> 2);
        bp[i] = (lo ? p.lo : p.hi) + (f & 3) * 8;
        bd[i] = (u32)((lo ? BLO : BHI) + (f >> 2) * 80 + (f & 3) * 16);
    }

    auto issue = [&](int ch, int stg) {
        const u32 st = sbase + (u32)(stg * SS);
        const int k0 = ch * KC;
        cpa16(st + AHI + adst0, Ah + aoff0 + k0);
        cpa16(st + AHI + adst1, Ah + aoff1 + k0);
        cpa16(st + ALO + adst0, Al + aoff0 + k0);
        cpa16(st + ALO + adst1, Al + aoff1 + k0);
#pragma unroll
        for (int i = 0; i < BITER; i++) cpa16(st + bd[i], bp[i] + k0);
        cp_commit();
    };

    // fragment lane addresses
    const int lane = tid & 31, w = tid >> 5;
    const int qq = lane >> 3, rr = lane & 7;
    const u32 aAddr = (u32)((16 * w + ((qq & 1) ? 8 : 0) + rr) * 80 + ((qq & 2) ? 16 : 0));
    const u32 bAddr = (u32)(rr * 80 + ((qq & 1) ? 16 : 0));

#pragma unroll
    for (int c = 0; c < S - 1; ++c) issue(c, c);

    int cstg = 0, pstg = S - 1;
    for (int ch = 0; ch < NCHUNK; ++ch) {
        asm volatile("cp.async.wait_group %0;" :: "n"(S - 2));
        __syncthreads();
        const u32 st = sbase + (u32)(cstg * SS);
#pragma unroll
        for (int k16 = 0; k16 < KC / 16; k16++) {
            const u32 ko = (u32)(k16 * 32);  // bytes
            u32 ah[4], al[4];
            ldmA(st + AHI + aAddr + ko, ah);
            ldmA(st + ALO + aAddr + ko, al);
#pragma unroll
            for (int j = 0; j < NB; j++) {
                u32 bh0, bh1, bl0, bl1;
                ldmB(st + BHI + (u32)(j * 640) + bAddr + ko, bh0, bh1);
                ldmB(st + BLO + (u32)(j * 640) + bAddr + ko, bl0, bl1);
                mma16816(acc[j][0], ah, bh0, bh1);
                mma16816(acc[j][1], ah, bl0, bl1);
                mma16816(acc[j][2], al, bh0, bh1);
            }
        }
        if (ch + S - 1 < NCHUNK) issue(ch + S - 1, pstg);
        else cp_commit();                 // keep committed count = ch + S
        pstg = cstg;
        cstg = (cstg + 1 == S) ? 0 : cstg + 1;
    }
}

constexpr int SMEM_NB2 = (10240 + 2 * 2 * 640) * S;   // 76800
constexpr int SMEM_NB4 = (10240 + 2 * 4 * 640) * S;   // 92160

#define ASUM(j, i) (acc[j][0][i] + acc[j][1][i] + acc[j][2][i])

// ---------------------------------------------------------------------------
// prep: split all static fp32 operands into bf16 hi/lo with padded pitch.
// ---------------------------------------------------------------------------
constexpr int U_W = 11000 * 250;
constexpr int U_DEC = 10000 * 250;
constexpr int U_EMB = 10000 * 250;
constexpr int U_HID = 64 * 250;
constexpr int U_WX = 1000 * 250;
constexpr int P0 = U_W;
constexpr int P1 = P0 + U_W;
constexpr int P2 = P1 + U_DEC;
constexpr int P3 = P2 + U_EMB;
constexpr int P4 = P3 + U_HID;
constexpr int P5 = P4 + U_WX;
constexpr int P6 = P5 + U_WX;
constexpr int PREP_UNITS = P6;

__device__ __forceinline__ void split4_store(float4 v, bf16* hi, bf16* lo, size_t o) {
    bf16 h0, l0, h1, l1, h2, l2, h3, l3;
    split1(v.x, h0, l0); split1(v.y, h1, l1); split1(v.z, h2, l2); split1(v.w, h3, l3);
    *(uint2*)&hi[o] = make_uint2(b2u(h0, h1), b2u(h2, h3));
    *(uint2*)&lo[o] = make_uint2(b2u(l0, l1), b2u(l2, l3));
}

__global__ __launch_bounds__(256) void prep_split(
    const float* __restrict__ Wh, const float* __restrict__ Wc,
    const float* __restrict__ dec_w, const float* __restrict__ emb,
    const float* __restrict__ hidden,
    const float* __restrict__ w_xh, const float* __restrict__ w_xc)
{
    int i = blockIdx.x * 256 + threadIdx.x;
    if (i >= PREP_UNITS) return;
    if (i < P0) {
        int row = i / 250, col = (i % 250) * 4;
        split4_store(*(const float4*)(Wh + (size_t)row * 1000 + col),
                     g_Whhi, g_Whlo, (size_t)row * KP + col);
    } else if (i < P1) {
        int j = i - P0; int row = j / 250, col = (j % 250) * 4;
        split4_store(*(const float4*)(Wc + (size_t)row * 1000 + col),
                     g_Wchi, g_Wclo, (size_t)row * KP + col);
    } else if (i < P2) {
        int j = i - P1; int row = j / 250, col = (j % 250) * 4;
        split4_store(*(const float4*)(dec_w + (size_t)row * 1000 + col),
                     g_dechi, g_declo, (size_t)row * KP + col);
    } else if (i < P3) {
        int j = i - P2; int row = j / 250, col = (j % 250) * 4;
        split4_store(*(const float4*)(emb + (size_t)row * 1000 + col),
                     g_embhi, g_emblo, (size_t)row * KP + col);
    } else if (i < P4) {
        int j = i - P3; int row = j / 250, col = (j % 250) * 4;
        split4_store(*(const float4*)(hidden + (size_t)row * 1000 + col),
                     g_hhi[11], g_hlo[11], (size_t)row * KP + col);
    } else if (i < P5) {
        int j = i - P4; int row = j / 250, col = (j % 250) * 4;
        split4_store(*(const float4*)(w_xh + (size_t)row * 2000 + col),
                     g_wxhe_hi, g_wxhe_lo, (size_t)row * KP + col);
        split4_store(*(const float4*)(w_xh + (size_t)row * 2000 + 1000 + col),
                     g_wxhh_hi, g_wxhh_lo, (size_t)row * KP + col);
    } else {
        int j = i - P5; int row = j / 250, col = (j % 250) * 4;
        split4_store(*(const float4*)(w_xc + (size_t)row * 2000 + col),
                     g_wxce_hi, g_wxce_lo, (size_t)row * KP + col);
        split4_store(*(const float4*)(w_xc + (size_t)row * 2000 + 1000 + col),
                     g_wxch_hi, g_wxch_lo, (size_t)row * KP + col);
    }
}

// ---------------------------------------------------------------------------
// precomp: P{h,c} = gather(emb) @ w_x{h,c}_embpart^T + bias, all T*B rows.
// grid (125, 64).
// ---------------------------------------------------------------------------
__global__ __launch_bounds__(128) void precomp_mma(
    const int* __restrict__ inputs,
    const float* __restrict__ b_xh, const float* __restrict__ b_xc)
{
    extern __shared__ char smem[];
    __shared__ int toks[64];
    const int m0 = blockIdx.y * 64;
    if (threadIdx.x < 64) toks[threadIdx.x] = inputs[m0 + threadIdx.x];
    __syncthreads();

    const int n0 = blockIdx.x * 8;
    float acc[2][3][4] = {};
    run_pipeline<2>(smem, g_embhi, g_emblo,
        [&](int m) { return toks[m]; },
        [&](int row) {
            size_t n = (size_t)(n0 + (row & 7)) * KP;
            return (row < 8) ? BPtr{ g_wxhe_hi + n, g_wxhe_lo + n }
                             : BPtr{ g_wxce_hi + n, g_wxce_lo + n };
        }, acc);

    const int w = threadIdx.x >> 5, lane = threadIdx.x & 31;
    const int g = lane >> 2, tq = lane & 3;
#pragma unroll
    for (int r = 0; r < 2; r++) {
        const int m = m0 + 16 * w + g + 8 * r;
        const int n = n0 + 2 * tq;
        const size_t idx = (size_t)m * Hd + n;
        float2 bh = *(const float2*)&b_xh[n];
        float2 bc = *(const float2*)&b_xc[n];
        *(float2*)&g_Ph[idx] = make_float2(ASUM(0, 2 * r) + bh.x, ASUM(0, 2 * r + 1) + bh.y);
        *(float2*)&g_Pc[idx] = make_float2(ASUM(1, 2 * r) + bc.x, ASUM(1, 2 * r + 1) + bc.y);
    }
}

// ---------------------------------------------------------------------------
// cell0: dual GEMM vs h_prev (K=1000) + precomputed emb part. grid 125.
// ---------------------------------------------------------------------------
__global__ __launch_bounds__(128) void cell0_mma(const float* __restrict__ hidden, int t)
{
    extern __shared__ char smem[];
    const float* __restrict__ hprev = (t == 0) ? hidden : g_h[11];
    const int n0 = blockIdx.x * 8;
    float acc[2][3][4] = {};
    run_pipeline<2>(smem, g_hhi[11], g_hlo[11],
        [](int m) { return m; },
        [&](int row) {
            size_t n = (size_t)(n0 + (row & 7)) * KP;
            return (row < 8) ? BPtr{ g_wxhh_hi + n, g_wxhh_lo + n }
                             : BPtr{ g_wxch_hi + n, g_wxch_lo + n };
        }, acc);

    const int w = threadIdx.x >> 5, lane = threadIdx.x & 31;
    const int g = lane >> 2, tq = lane & 3;
#pragma unroll
    for (int r = 0; r < 2; r++) {
        const int m = 16 * w + g + 8 * r;
        const int n = n0 + 2 * tq;
        const int idx = m * Hd + n;
        const size_t pidx = (size_t)(t * Bb + m) * Hd + n;
        float2 ph = *(const float2*)&g_Ph[pidx];
        float2 pc = *(const float2*)&g_Pc[pidx];
        float2 hp = *(const float2*)&hprev[idx];
        float c0a = sigmf(ASUM(1, 2 * r) + pc.x);
        float c0b = sigmf(ASUM(1, 2 * r + 1) + pc.y);
        float h0a = c0a * tanhf(ASUM(0, 2 * r) + ph.x) + (1.0f - c0a) * hp.x;
        float h0b = c0b * tanhf(ASUM(0, 2 * r + 1) + ph.y) + (1.0f - c0b) * hp.y;
        *(float2*)&g_c0[idx] = make_float2(c0a, c0b);
        *(float2*)&g_h[0][idx] = make_float2(h0a, h0b);
        bf16 ha, la, hb, lb;
        split1(h0a, ha, la); split1(h0b, hb, lb);
        const size_t sidx = (size_t)m * KP + n;
        *(u32*)&g_hhi[0][sidx] = b2u(ha, hb);
        *(u32*)&g_hlo[0][sidx] = b2u(la, lb);
    }
}

// ---------------------------------------------------------------------------
// Generic DAG level. grid = (125, n_edges).
// ---------------------------------------------------------------------------
__global__ __launch_bounds__(128) void level_mma(LevelDesc L)
{
    extern __shared__ char smem[];
    const EdgeDesc ed = L.e[blockIdx.y];
    const float* __restrict__ hin = g_h[ed.parent];
    float* __restrict__ hout = g_h[ed.child];
    const bf16* whh = g_Whhi + (size_t)ed.w * 1000 * KP;
    const bf16* whl = g_Whlo + (size_t)ed.w * 1000 * KP;
    const bf16* wch = g_Wchi + (size_t)ed.w * 1000 * KP;
    const bf16* wcl = g_Wclo + (size_t)ed.w * 1000 * KP;
    const int n0 = blockIdx.x * 8;

    float acc[2][3][4] = {};
    run_pipeline<2>(smem, g_hhi[ed.parent], g_hlo[ed.parent],
        [](int m) { return m; },
        [&](int row) {
            size_t n = (size_t)(n0 + (row & 7)) * KP;
            return (row < 8) ? BPtr{ whh + n, whl + n } : BPtr{ wch + n, wcl + n };
        }, acc);

    const int w = threadIdx.x >> 5, lane = threadIdx.x & 31;
    const int g = lane >> 2, tq = lane & 3;
#pragma unroll
    for (int r = 0; r < 2; r++) {
        const int m = 16 * w + g + 8 * r;
        const int n = n0 + 2 * tq;
        const int idx = m * Hd + n;
        float2 hi2 = *(const float2*)&hin[idx];
        float2 c02 = *(const float2*)&g_c0[idx];
        float oa = sigmf(ASUM(1, 2 * r)) * applyAct(ed.act, ASUM(0, 2 * r))
                   + (1.0f - c02.x) * hi2.x;
        float ob = sigmf(ASUM(1, 2 * r + 1)) * applyAct(ed.act, ASUM(0, 2 * r + 1))
                   + (1.0f - c02.y) * hi2.y;
        *(float2*)&hout[idx] = make_float2(oa, ob);
        if (ed.split) {
            bf16 ha, la, hb, lb;
            split1(oa, ha, la); split1(ob, hb, lb);
            const size_t sidx = (size_t)m * KP + n;
            *(u32*)&g_hhi[ed.child][sidx] = b2u(ha, hb);
            *(u32*)&g_hlo[ed.child][sidx] = b2u(la, lb);
        }
    }
}

// ---------------------------------------------------------------------------
// Last level fused: edges 8 (4->5, relu) and 9 (4->11, sigmoid) + leaf mean.
// NB=4 groups: [Wh8, Wc8, Wh9, Wc9]. grid 125.
// ---------------------------------------------------------------------------
__global__ __launch_bounds__(128) void last_mma(int t)
{
    extern __shared__ char smem[];
    const int n0 = blockIdx.x * 8;
    const bf16* base_hi[4] = { g_Whhi + (size_t)8 * 1000 * KP, g_Wchi + (size_t)8 * 1000 * KP,
                               g_Whhi + (size_t)9 * 1000 * KP, g_Wchi + (size_t)9 * 1000 * KP };
    const bf16* base_lo[4] = { g_Whlo + (size_t)8 * 1000 * KP, g_Wclo + (size_t)8 * 1000 * KP,
                               g_Whlo + (size_t)9 * 1000 * KP, g_Wclo + (size_t)9 * 1000 * KP };

    float acc[4][3][4] = {};
    run_pipeline<4>(smem, g_hhi[4], g_hlo[4],
        [](int m) { return m; },
        [&](int row) {
            int mat = row >> 3;
            size_t n = (size_t)(n0 + (row & 7)) * KP;
            return BPtr{ base_hi[mat] + n, base_lo[mat] + n };
        }, acc);

    const int w = threadIdx.x >> 5, lane = threadIdx.x & 31;
    const int g = lane >> 2, tq = lane & 3;
#pragma unroll
    for (int r = 0; r < 2; r++) {
        const int m = 16 * w + g + 8 * r;
        const int n = n0 + 2 * tq;
        const int idx = m * Hd + n;
        float2 h4v = *(const float2*)&g_h[4][idx];
        float2 c02 = *(const float2*)&g_c0[idx];
        float oma = 1.0f - c02.x, omb = 1.0f - c02.y;
        float h5a  = sigmf(ASUM(1, 2 * r))     * fmaxf(ASUM(0, 2 * r), 0.0f)     + oma * h4v.x;
        float h5b  = sigmf(ASUM(1, 2 * r + 1)) * fmaxf(ASUM(0, 2 * r + 1), 0.0f) + omb * h4v.y;
        float h11a = sigmf(ASUM(3, 2 * r))     * sigmf(ASUM(2, 2 * r))           + oma * h4v.x;
        float h11b = sigmf(ASUM(3, 2 * r + 1)) * sigmf(ASUM(2, 2 * r + 1))       + omb * h4v.y;
        *(float2*)&g_h[11][idx] = make_float2(h11a, h11b);
        bf16 ha, la, hb, lb;
        split1(h11a, ha, la); split1(h11b, hb, lb);
        const size_t sidx = (size_t)m * KP + n;
        *(u32*)&g_hhi[11][sidx] = b2u(ha, hb);
        *(u32*)&g_hlo[11][sidx] = b2u(la, lb);

        float2 h7 = *(const float2*)&g_h[7][idx];
        float2 h8 = *(const float2*)&g_h[8][idx];
        float2 h9 = *(const float2*)&g_h[9][idx];
        float2 hA = *(const float2*)&g_h[10][idx];
        float oa = (h5a + h11a + h7.x + h8.x + h9.x + hA.x) * (1.0f / 6.0f);
        float ob = (h5b + h11b + h7.y + h8.y + h9.y + hA.y) * (1.0f / 6.0f);
        split1(oa, ha, la); split1(ob, hb, lb);
        const size_t oidx = (size_t)(t * Bb + m) * KP + n;
        *(u32*)&g_outshi[oidx] = b2u(ha, hb);
        *(u32*)&g_outslo[oidx] = b2u(la, lb);
    }
}

// ---------------------------------------------------------------------------
// Decoder: out[m][v] = outs[m] . dec_w[v] + dec_b[v]; grid (625, 64).
// NB=2: 16 consecutive n per CTA.
// ---------------------------------------------------------------------------
__global__ __launch_bounds__(128) void decoder_mma(
    const float* __restrict__ dec_b, float* __restrict__ out)
{
    extern __shared__ char smem[];
    const int n0 = blockIdx.x * 16;
    const int m0 = blockIdx.y * 64;
    float acc[2][3][4] = {};
    run_pipeline<2>(smem, g_outshi, g_outslo,
        [&](int m) { return m0 + m; },
        [&](int row) {
            size_t n = (size_t)(n0 + row) * KP;
            return BPtr{ g_dechi + n, g_declo + n };
        }, acc);

    const int w = threadIdx.x >> 5, lane = threadIdx.x & 31;
    const int g = lane >> 2, tq = lane & 3;
#pragma unroll
    for (int j = 0; j < 2; j++)
#pragma unroll
        for (int r = 0; r < 2; r++) {
            const int m = m0 + 16 * w + g + 8 * r;
            const int n = n0 + j * 8 + 2 * tq;
            float2 db = *(const float2*)&dec_b[n];
            *(float2*)&out[(size_t)m * Vv + n] =
                make_float2(ASUM(j, 2 * r) + db.x, ASUM(j, 2 * r + 1) + db.y);
        }
}

} // namespace

// ---------------------------------------------------------------------------
extern "C" void kernel_launch(void* const* d_in, const int* in_sizes, int n_in,
                              void* d_out, int out_size)
{
    (void)in_sizes; (void)n_in; (void)out_size;

    const int*   inputs = (const int*)  d_in[0];
    const float* hidden = (const float*)d_in[1];
    const float* emb    = (const float*)d_in[2];
    const float* w_xh   = (const float*)d_in[3];
    const float* b_xh   = (const float*)d_in[4];
    const float* w_xc   = (const float*)d_in[5];
    const float* b_xc   = (const float*)d_in[6];
    const float* Wh     = (const float*)d_in[7];
    const float* Wc     = (const float*)d_in[8];
    const float* dec_w  = (const float*)d_in[9];
    const float* dec_b  = (const float*)d_in[10];
    float* out = (float*)d_out;

    cudaFuncSetAttribute(precomp_mma, cudaFuncAttributeMaxDynamicSharedMemorySize, SMEM_NB2);
    cudaFuncSetAttribute(cell0_mma,   cudaFuncAttributeMaxDynamicSharedMemorySize, SMEM_NB2);
    cudaFuncSetAttribute(level_mma,   cudaFuncAttributeMaxDynamicSharedMemorySize, SMEM_NB2);
    cudaFuncSetAttribute(last_mma,    cudaFuncAttributeMaxDynamicSharedMemorySize, SMEM_NB4);
    cudaFuncSetAttribute(decoder_mma, cudaFuncAttributeMaxDynamicSharedMemorySize, SMEM_NB2);

    // acts: 0=relu, 1=tanh, 2=sigmoid, 3=identity; split=1 if child is a parent
    const LevelDesc LV1 = {{ {0, 1, 0, 0, 1},  {0, 6, 1, 1, 1},  {0, 0, 0, 3, 0} }};
    const LevelDesc LV2 = {{ {1, 2, 2, 0, 1},  {1, 8, 3, 2, 0},  {6, 7, 10, 1, 0} }};
    const LevelDesc LV3 = {{ {2, 3, 4, 1, 1},  {2, 9, 5, 0, 0},  {0, 0, 0, 3, 0} }};
    const LevelDesc LV4 = {{ {3, 4, 6, 3, 1},  {3, 10, 7, 1, 0}, {0, 0, 0, 3, 0} }};

    prep_split<<<(PREP_UNITS + 255) / 256, 256>>>(Wh, Wc, dec_w, emb, hidden, w_xh, w_xc);
    precomp_mma<<<dim3(125, 64), 128, SMEM_NB2>>>(inputs, b_xh, b_xc);

    for (int t = 0; t < Tt; ++t) {
        cell0_mma<<<125, 128, SMEM_NB2>>>(hidden, t);
        level_mma<<<dim3(125, 2), 128, SMEM_NB2>>>(LV1);
        level_mma<<<dim3(125, 3), 128, SMEM_NB2>>>(LV2);
        level_mma<<<dim3(125, 2), 128, SMEM_NB2>>>(LV3);
        level_mma<<<dim3(125, 2), 128, SMEM_NB2>>>(LV4);
        last_mma<<<125, 128, SMEM_NB4>>>(t);
    }

    decoder_mma<<<dim3(625, 64), 128, SMEM_NB2>>>(dec_b, out);
}

// round 7
// speedup vs baseline: 1.0432x; 1.0432x over previous
#include <cuda_runtime.h>
#include <cuda_bf16.h>

// ---------------------------------------------------------------------------
// ENAS RNN — round 7: 8-warp CTAs with warp-level n-split over shared smem
// stages, prefetch issued before compute, S=6. bf16 3-term split, fp32 accum.
// ---------------------------------------------------------------------------

namespace {

typedef unsigned int u32;
typedef __nv_bfloat16 bf16;

constexpr int Hd = 1000;
constexpr int Bb = 64;
constexpr int Tt = 64;
constexpr int Vv = 10000;

constexpr int KP = 1024;          // padded K pitch (elements)
constexpr int S = 6;              // pipeline stages
constexpr int KC = 32;            // k per chunk
constexpr int NCHUNK = KP / KC;   // 32

// ---------------- static device storage (zero-initialized at load) ---------
__device__ bf16 g_Whhi[11 * 1000 * KP], g_Whlo[11 * 1000 * KP];
__device__ bf16 g_Wchi[11 * 1000 * KP], g_Wclo[11 * 1000 * KP];
__device__ bf16 g_dechi[10000 * KP], g_declo[10000 * KP];
__device__ bf16 g_embhi[10000 * KP], g_emblo[10000 * KP];
__device__ bf16 g_wxhe_hi[1000 * KP], g_wxhe_lo[1000 * KP];
__device__ bf16 g_wxhh_hi[1000 * KP], g_wxhh_lo[1000 * KP];
__device__ bf16 g_wxce_hi[1000 * KP], g_wxce_lo[1000 * KP];
__device__ bf16 g_wxch_hi[1000 * KP], g_wxch_lo[1000 * KP];

__device__ float g_h[12][Bb * Hd];
__device__ bf16  g_hhi[12][Bb * KP];
__device__ bf16  g_hlo[12][Bb * KP];
__device__ float g_c0[Bb * Hd];
__device__ float g_Ph[Tt * Bb * Hd];
__device__ float g_Pc[Tt * Bb * Hd];
__device__ bf16  g_outshi[Tt * Bb * KP];
__device__ bf16  g_outslo[Tt * Bb * KP];

// ---------------- helpers ---------------------------------------------------
__device__ __forceinline__ float sigmf(float x) { return 1.0f / (1.0f + expf(-x)); }

__device__ __forceinline__ float applyAct(int a, float v) {
    switch (a) {
        case 0: return fmaxf(v, 0.0f);
        case 1: return tanhf(v);
        case 2: return sigmf(v);
        default: return v;
    }
}

__device__ __forceinline__ void split1(float x, bf16& h, bf16& l) {
    h = __float2bfloat16(x);
    l = __float2bfloat16(x - __bfloat162float(h));
}
__device__ __forceinline__ u32 b2u(bf16 a, bf16 b) {
    return (u32)__bfloat16_as_ushort(a) | ((u32)__bfloat16_as_ushort(b) << 16);
}

__device__ __forceinline__ void mma16816(float (&d)[4], const u32 (&a)[4], u32 b0, u32 b1) {
    asm volatile(
        "mma.sync.aligned.m16n8k16.row.col.f32.bf16.bf16.f32 "
        "{%0,%1,%2,%3}, {%4,%5,%6,%7}, {%8,%9}, {%0,%1,%2,%3};"
        : "+f"(d[0]), "+f"(d[1]), "+f"(d[2]), "+f"(d[3])
        : "r"(a[0]), "r"(a[1]), "r"(a[2]), "r"(a[3]), "r"(b0), "r"(b1));
}
__device__ __forceinline__ void ldmA(u32 a, u32 (&r)[4]) {
    asm volatile("ldmatrix.sync.aligned.m8n8.x4.shared.b16 {%0,%1,%2,%3}, [%4];"
                 : "=r"(r[0]), "=r"(r[1]), "=r"(r[2]), "=r"(r[3]) : "r"(a));
}
__device__ __forceinline__ void ldmB(u32 a, u32& b0, u32& b1) {
    asm volatile("ldmatrix.sync.aligned.m8n8.x2.shared.b16 {%0,%1}, [%2];"
                 : "=r"(b0), "=r"(b1) : "r"(a));
}
__device__ __forceinline__ void cpa16(u32 dst, const void* src) {
    asm volatile("cp.async.cg.shared.global [%0], [%1], 16;" :: "r"(dst), "l"(src));
}
__device__ __forceinline__ void cp_commit() { asm volatile("cp.async.commit_group;"); }

struct BPtr { const bf16* hi; const bf16* lo; };
struct EdgeDesc { int parent; int child; int w; int act; int split; };
struct LevelDesc { EdgeDesc e[3]; };

// ---------------------------------------------------------------------------
// 8-warp pipelined GEMM mainloop. A: 64 x KP bf16 hi/lo (row via arow).
// B: NB groups of 8 rows. Warps: mw = warp&3 owns m [16mw,16mw+16);
// ng = warp>>2 owns B-groups [ng*NB/2, (ng+1)*NB/2).
// acc[jj][t]: own group jj, split-term t. D = Ahi*Bhi + Ahi*Blo + Alo*Bhi.
// Commit-count invariant: entering iter ch, committed = ch + (S-1); the
// prefetch for ch+S-1 is issued BEFORE compute (stage (ch-1)%S is free after
// the top barrier), maximizing load lead time.
// ---------------------------------------------------------------------------
template <int NB, class AROW, class BSRC>
__device__ __forceinline__ void run_pipeline(
    char* smem, const bf16* __restrict__ Ah, const bf16* __restrict__ Al,
    AROW arow, BSRC bsrc, float (&acc)[NB / 2][3][4])
{
    constexpr int NGRP = NB / 2;
    constexpr int AHI = 0, ALO = 5120, BHI = 10240, BLO = 10240 + NB * 640;
    constexpr int SS = 10240 + 2 * NB * 640;

    const int tid = threadIdx.x;
    const u32 sbase = (u32)__cvta_generic_to_shared(smem);

    // A: one 16B vector per precision per thread (256 vecs per precision).
    const size_t aoff = (size_t)arow(tid >> 2) * KP + (tid & 3) * 8;
    const u32 adst = (u32)((tid >> 2) * 80 + (tid & 3) * 16);

    // B: NB*64 vectors total (hi then lo), one per thread where valid.
    const bool bval = tid < NB * 64;
    const int e = bval ? tid : 0;
    const bool blo = e >= NB * 32;
    const int f = blo ? e - NB * 32 : e;
    BPtr p = bsrc(f >> 2);
    const bf16* bp = (blo ? p.lo : p.hi) + (f & 3) * 8;
    const u32 bd = (u32)((blo ? BLO : BHI) + (f >> 2) * 80 + (f & 3) * 16);

    auto issue = [&](int ch) {
        const u32 st = sbase + (u32)((ch % S) * SS);
        const int k0 = ch * KC;
        cpa16(st + AHI + adst, Ah + aoff + k0);
        cpa16(st + ALO + adst, Al + aoff + k0);
        if (bval) cpa16(st + bd, bp + k0);
        cp_commit();
    };

    const int lane = tid & 31;
    const int mw = (tid >> 5) & 3, ng = tid >> 7;
    const int qq = lane >> 3, rr = lane & 7;
    const u32 aAddr = (u32)((16 * mw + ((qq & 1) ? 8 : 0) + rr) * 80 + ((qq & 2) ? 16 : 0));
    const u32 bAddr = (u32)(rr * 80 + ((qq & 1) ? 16 : 0));

#pragma unroll
    for (int c = 0; c < S - 1; ++c) issue(c);

    for (int ch = 0; ch < NCHUNK; ++ch) {
        asm volatile("cp.async.wait_group %0;" :: "n"(S - 2));
        __syncthreads();
        if (ch + S - 1 < NCHUNK) issue(ch + S - 1);
        else cp_commit();                 // keep commit count = ch + S
        const u32 st = sbase + (u32)((ch % S) * SS);
#pragma unroll
        for (int k16 = 0; k16 < KC / 16; k16++) {
            const u32 ko = (u32)(k16 * 32);  // bytes
            u32 ah[4], al[4];
            ldmA(st + AHI + aAddr + ko, ah);
            ldmA(st + ALO + aAddr + ko, al);
#pragma unroll
            for (int jj = 0; jj < NGRP; jj++) {
                const int j = ng * NGRP + jj;
                u32 bh0, bh1, bl0, bl1;
                ldmB(st + BHI + (u32)(j * 640) + bAddr + ko, bh0, bh1);
                ldmB(st + BLO + (u32)(j * 640) + bAddr + ko, bl0, bl1);
                mma16816(acc[jj][0], ah, bh0, bh1);
                mma16816(acc[jj][1], ah, bl0, bl1);
                mma16816(acc[jj][2], al, bh0, bh1);
            }
        }
    }
    __syncthreads();   // smem stages now dead; reusable for epilogue exchange
}

constexpr int SMEM_NB2 = (10240 + 2 * 2 * 640) * S;   // 76800
constexpr int SMEM_NB4 = (10240 + 2 * 4 * 640) * S;   // 92160

// Store a warp's 3-term-summed acc group into exchange smem: ex[jj][m 0..63][n 0..7]
__device__ __forceinline__ void ex_store(float* ex, int jj, const float (&a)[3][4],
                                         int mw, int lane) {
    const int g = lane >> 2, tq = lane & 3;
#pragma unroll
    for (int r = 0; r < 2; r++) {
        float2 v = make_float2(a[0][2 * r] + a[1][2 * r] + a[2][2 * r],
                               a[0][2 * r + 1] + a[1][2 * r + 1] + a[2][2 * r + 1]);
        *(float2*)&ex[jj * 512 + (16 * mw + g + 8 * r) * 8 + 2 * tq] = v;
    }
}

#define ASUM(jj, i) (acc[jj][0][i] + acc[jj][1][i] + acc[jj][2][i])

// ---------------------------------------------------------------------------
// prep: split all static fp32 operands into bf16 hi/lo with padded pitch.
// ---------------------------------------------------------------------------
constexpr int U_W = 11000 * 250;
constexpr int U_DEC = 10000 * 250;
constexpr int U_EMB = 10000 * 250;
constexpr int U_HID = 64 * 250;
constexpr int U_WX = 1000 * 250;
constexpr int P0 = U_W;
constexpr int P1 = P0 + U_W;
constexpr int P2 = P1 + U_DEC;
constexpr int P3 = P2 + U_EMB;
constexpr int P4 = P3 + U_HID;
constexpr int P5 = P4 + U_WX;
constexpr int P6 = P5 + U_WX;
constexpr int PREP_UNITS = P6;

__device__ __forceinline__ void split4_store(float4 v, bf16* hi, bf16* lo, size_t o) {
    bf16 h0, l0, h1, l1, h2, l2, h3, l3;
    split1(v.x, h0, l0); split1(v.y, h1, l1); split1(v.z, h2, l2); split1(v.w, h3, l3);
    *(uint2*)&hi[o] = make_uint2(b2u(h0, h1), b2u(h2, h3));
    *(uint2*)&lo[o] = make_uint2(b2u(l0, l1), b2u(l2, l3));
}

__global__ __launch_bounds__(256) void prep_split(
    const float* __restrict__ Wh, const float* __restrict__ Wc,
    const float* __restrict__ dec_w, const float* __restrict__ emb,
    const float* __restrict__ hidden,
    const float* __restrict__ w_xh, const float* __restrict__ w_xc)
{
    int i = blockIdx.x * 256 + threadIdx.x;
    if (i >= PREP_UNITS) return;
    if (i < P0) {
        int row = i / 250, col = (i % 250) * 4;
        split4_store(*(const float4*)(Wh + (size_t)row * 1000 + col),
                     g_Whhi, g_Whlo, (size_t)row * KP + col);
    } else if (i < P1) {
        int j = i - P0; int row = j / 250, col = (j % 250) * 4;
        split4_store(*(const float4*)(Wc + (size_t)row * 1000 + col),
                     g_Wchi, g_Wclo, (size_t)row * KP + col);
    } else if (i < P2) {
        int j = i - P1; int row = j / 250, col = (j % 250) * 4;
        split4_store(*(const float4*)(dec_w + (size_t)row * 1000 + col),
                     g_dechi, g_declo, (size_t)row * KP + col);
    } else if (i < P3) {
        int j = i - P2; int row = j / 250, col = (j % 250) * 4;
        split4_store(*(const float4*)(emb + (size_t)row * 1000 + col),
                     g_embhi, g_emblo, (size_t)row * KP + col);
    } else if (i < P4) {
        int j = i - P3; int row = j / 250, col = (j % 250) * 4;
        split4_store(*(const float4*)(hidden + (size_t)row * 1000 + col),
                     g_hhi[11], g_hlo[11], (size_t)row * KP + col);
    } else if (i < P5) {
        int j = i - P4; int row = j / 250, col = (j % 250) * 4;
        split4_store(*(const float4*)(w_xh + (size_t)row * 2000 + col),
                     g_wxhe_hi, g_wxhe_lo, (size_t)row * KP + col);
        split4_store(*(const float4*)(w_xh + (size_t)row * 2000 + 1000 + col),
                     g_wxhh_hi, g_wxhh_lo, (size_t)row * KP + col);
    } else {
        int j = i - P5; int row = j / 250, col = (j % 250) * 4;
        split4_store(*(const float4*)(w_xc + (size_t)row * 2000 + col),
                     g_wxce_hi, g_wxce_lo, (size_t)row * KP + col);
        split4_store(*(const float4*)(w_xc + (size_t)row * 2000 + 1000 + col),
                     g_wxch_hi, g_wxch_lo, (size_t)row * KP + col);
    }
}

// ---------------------------------------------------------------------------
// precomp: P{h,c} = gather(emb) @ w_x{h,c}_embpart^T + bias. grid (125, 64).
// Groups: 0 -> Ph (warps 0-3 write), 1 -> Pc (warps 4-7 write). No exchange.
// ---------------------------------------------------------------------------
__global__ __launch_bounds__(256) void precomp_mma(
    const int* __restrict__ inputs,
    const float* __restrict__ b_xh, const float* __restrict__ b_xc)
{
    extern __shared__ char smem[];
    __shared__ int toks[64];
    const int m0 = blockIdx.y * 64;
    if (threadIdx.x < 64) toks[threadIdx.x] = inputs[m0 + threadIdx.x];
    __syncthreads();

    const int n0 = blockIdx.x * 8;
    float acc[1][3][4] = {};
    run_pipeline<2>(smem, g_embhi, g_emblo,
        [&](int m) { return toks[m]; },
        [&](int row) {
            size_t n = (size_t)(n0 + (row & 7)) * KP;
            return (row < 8) ? BPtr{ g_wxhe_hi + n, g_wxhe_lo + n }
                             : BPtr{ g_wxce_hi + n, g_wxce_lo + n };
        }, acc);

    const int lane = threadIdx.x & 31;
    const int mw = (threadIdx.x >> 5) & 3, ng = threadIdx.x >> 7;
    const int g = lane >> 2, tq = lane & 3;
    const float* bias = ng ? b_xc : b_xh;
    float* dst = ng ? g_Pc : g_Ph;
#pragma unroll
    for (int r = 0; r < 2; r++) {
        const int m = m0 + 16 * mw + g + 8 * r;
        const int n = n0 + 2 * tq;
        float2 bb = *(const float2*)&bias[n];
        *(float2*)&dst[(size_t)m * Hd + n] =
            make_float2(ASUM(0, 2 * r) + bb.x, ASUM(0, 2 * r + 1) + bb.y);
    }
}

// ---------------------------------------------------------------------------
// cell0: dual GEMM vs h_prev (K=1000) + precomputed emb part. grid 125.
// ---------------------------------------------------------------------------
__global__ __launch_bounds__(256) void cell0_mma(const float* __restrict__ hidden, int t)
{
    extern __shared__ char smem[];
    const float* __restrict__ hprev = (t == 0) ? hidden : g_h[11];
    const int n0 = blockIdx.x * 8;
    float acc[1][3][4] = {};
    run_pipeline<2>(smem, g_hhi[11], g_hlo[11],
        [](int m) { return m; },
        [&](int row) {
            size_t n = (size_t)(n0 + (row & 7)) * KP;
            return (row < 8) ? BPtr{ g_wxhh_hi + n, g_wxhh_lo + n }
                             : BPtr{ g_wxch_hi + n, g_wxch_lo + n };
        }, acc);

    float* ex = (float*)smem;
    const int lane = threadIdx.x & 31;
    const int mw = (threadIdx.x >> 5) & 3, ng = threadIdx.x >> 7;
    const int g = lane >> 2, tq = lane & 3;
    if (ng == 1) ex_store(ex, 0, acc[0], mw, lane);   // Wc sums
    __syncthreads();
    if (ng == 0) {
#pragma unroll
        for (int r = 0; r < 2; r++) {
            const int m = 16 * mw + g + 8 * r;
            const int n = n0 + 2 * tq;
            const int idx = m * Hd + n;
            const size_t pidx = (size_t)(t * Bb + m) * Hd + n;
            float2 sc = *(const float2*)&ex[(16 * mw + g + 8 * r) * 8 + 2 * tq];
            float2 ph = *(const float2*)&g_Ph[pidx];
            float2 pc = *(const float2*)&g_Pc[pidx];
            float2 hp = *(const float2*)&hprev[idx];
            float c0a = sigmf(sc.x + pc.x);
            float c0b = sigmf(sc.y + pc.y);
            float h0a = c0a * tanhf(ASUM(0, 2 * r) + ph.x) + (1.0f - c0a) * hp.x;
            float h0b = c0b * tanhf(ASUM(0, 2 * r + 1) + ph.y) + (1.0f - c0b) * hp.y;
            *(float2*)&g_c0[idx] = make_float2(c0a, c0b);
            *(float2*)&g_h[0][idx] = make_float2(h0a, h0b);
            bf16 ha, la, hb, lb;
            split1(h0a, ha, la); split1(h0b, hb, lb);
            const size_t sidx = (size_t)m * KP + n;
            *(u32*)&g_hhi[0][sidx] = b2u(ha, hb);
            *(u32*)&g_hlo[0][sidx] = b2u(la, lb);
        }
    }
}

// ---------------------------------------------------------------------------
// Generic DAG level. grid = (125, n_edges).
// ---------------------------------------------------------------------------
__global__ __launch_bounds__(256) void level_mma(LevelDesc L)
{
    extern __shared__ char smem[];
    const EdgeDesc ed = L.e[blockIdx.y];
    const float* __restrict__ hin = g_h[ed.parent];
    float* __restrict__ hout = g_h[ed.child];
    const bf16* whh = g_Whhi + (size_t)ed.w * 1000 * KP;
    const bf16* whl = g_Whlo + (size_t)ed.w * 1000 * KP;
    const bf16* wch = g_Wchi + (size_t)ed.w * 1000 * KP;
    const bf16* wcl = g_Wclo + (size_t)ed.w * 1000 * KP;
    const int n0 = blockIdx.x * 8;

    float acc[1][3][4] = {};
    run_pipeline<2>(smem, g_hhi[ed.parent], g_hlo[ed.parent],
        [](int m) { return m; },
        [&](int row) {
            size_t n = (size_t)(n0 + (row & 7)) * KP;
            return (row < 8) ? BPtr{ whh + n, whl + n } : BPtr{ wch + n, wcl + n };
        }, acc);

    float* ex = (float*)smem;
    const int lane = threadIdx.x & 31;
    const int mw = (threadIdx.x >> 5) & 3, ng = threadIdx.x >> 7;
    const int g = lane >> 2, tq = lane & 3;
    if (ng == 1) ex_store(ex, 0, acc[0], mw, lane);   // Wc sums
    __syncthreads();
    if (ng == 0) {
#pragma unroll
        for (int r = 0; r < 2; r++) {
            const int m = 16 * mw + g + 8 * r;
            const int n = n0 + 2 * tq;
            const int idx = m * Hd + n;
            float2 sc = *(const float2*)&ex[(16 * mw + g + 8 * r) * 8 + 2 * tq];
            float2 hi2 = *(const float2*)&hin[idx];
            float2 c02 = *(const float2*)&g_c0[idx];
            float oa = sigmf(sc.x) * applyAct(ed.act, ASUM(0, 2 * r))
                       + (1.0f - c02.x) * hi2.x;
            float ob = sigmf(sc.y) * applyAct(ed.act, ASUM(0, 2 * r + 1))
                       + (1.0f - c02.y) * hi2.y;
            *(float2*)&hout[idx] = make_float2(oa, ob);
            if (ed.split) {
                bf16 ha, la, hb, lb;
                split1(oa, ha, la); split1(ob, hb, lb);
                const size_t sidx = (size_t)m * KP + n;
                *(u32*)&g_hhi[ed.child][sidx] = b2u(ha, hb);
                *(u32*)&g_hlo[ed.child][sidx] = b2u(la, lb);
            }
        }
    }
}

// ---------------------------------------------------------------------------
// Last level fused: edges 8 (4->5, relu) and 9 (4->11, sigmoid) + leaf mean.
// NB=4 groups: [Wh8, Wc8 | Wh9, Wc9]; warps 0-3 own h5 pair, 4-7 own h11 pair.
// grid 125.
// ---------------------------------------------------------------------------
__global__ __launch_bounds__(256) void last_mma(int t)
{
    extern __shared__ char smem[];
    const int n0 = blockIdx.x * 8;
    const bf16* base_hi[4] = { g_Whhi + (size_t)8 * 1000 * KP, g_Wchi + (size_t)8 * 1000 * KP,
                               g_Whhi + (size_t)9 * 1000 * KP, g_Wchi + (size_t)9 * 1000 * KP };
    const bf16* base_lo[4] = { g_Whlo + (size_t)8 * 1000 * KP, g_Wclo + (size_t)8 * 1000 * KP,
                               g_Whlo + (size_t)9 * 1000 * KP, g_Wclo + (size_t)9 * 1000 * KP };

    float acc[2][3][4] = {};
    run_pipeline<4>(smem, g_hhi[4], g_hlo[4],
        [](int m) { return m; },
        [&](int row) {
            int mat = row >> 3;
            size_t n = (size_t)(n0 + (row & 7)) * KP;
            return BPtr{ base_hi[mat] + n, base_lo[mat] + n };
        }, acc);

    float* ex = (float*)smem;
    const int lane = threadIdx.x & 31;
    const int mw = (threadIdx.x >> 5) & 3, ng = threadIdx.x >> 7;
    const int g = lane >> 2, tq = lane & 3;
    if (ng == 1) {                         // Wh9, Wc9 sums
        ex_store(ex, 0, acc[0], mw, lane);
        ex_store(ex, 1, acc[1], mw, lane);
    }
    __syncthreads();
    if (ng == 0) {
#pragma unroll
        for (int r = 0; r < 2; r++) {
            const int m = 16 * mw + g + 8 * r;
            const int n = n0 + 2 * tq;
            const int idx = m * Hd + n;
            const int eo = (16 * mw + g + 8 * r) * 8 + 2 * tq;
            float2 s9h = *(const float2*)&ex[eo];          // Wh9
            float2 s9c = *(const float2*)&ex[512 + eo];    // Wc9
            float2 h4v = *(const float2*)&g_h[4][idx];
            float2 c02 = *(const float2*)&g_c0[idx];
            float oma = 1.0f - c02.x, omb = 1.0f - c02.y;
            float h5a  = sigmf(ASUM(1, 2 * r))     * fmaxf(ASUM(0, 2 * r), 0.0f)     + oma * h4v.x;
            float h5b  = sigmf(ASUM(1, 2 * r + 1)) * fmaxf(ASUM(0, 2 * r + 1), 0.0f) + omb * h4v.y;
            float h11a = sigmf(s9c.x) * sigmf(s9h.x) + oma * h4v.x;
            float h11b = sigmf(s9c.y) * sigmf(s9h.y) + omb * h4v.y;
            *(float2*)&g_h[11][idx] = make_float2(h11a, h11b);
            bf16 ha, la, hb, lb;
            split1(h11a, ha, la); split1(h11b, hb, lb);
            const size_t sidx = (size_t)m * KP + n;
            *(u32*)&g_hhi[11][sidx] = b2u(ha, hb);
            *(u32*)&g_hlo[11][sidx] = b2u(la, lb);

            float2 h7 = *(const float2*)&g_h[7][idx];
            float2 h8 = *(const float2*)&g_h[8][idx];
            float2 h9 = *(const float2*)&g_h[9][idx];
            float2 hA = *(const float2*)&g_h[10][idx];
            float oa = (h5a + h11a + h7.x + h8.x + h9.x + hA.x) * (1.0f / 6.0f);
            float ob = (h5b + h11b + h7.y + h8.y + h9.y + hA.y) * (1.0f / 6.0f);
            split1(oa, ha, la); split1(ob, hb, lb);
            const size_t oidx = (size_t)(t * Bb + m) * KP + n;
            *(u32*)&g_outshi[oidx] = b2u(ha, hb);
            *(u32*)&g_outslo[oidx] = b2u(la, lb);
        }
    }
}

// ---------------------------------------------------------------------------
// Decoder: out[m][v] = outs[m] . dec_w[v] + dec_b[v]; grid (625, 64).
// Groups are disjoint n-ranges; each warp writes its own. No exchange.
// ---------------------------------------------------------------------------
__global__ __launch_bounds__(256) void decoder_mma(
    const float* __restrict__ dec_b, float* __restrict__ out)
{
    extern __shared__ char smem[];
    const int n0 = blockIdx.x * 16;
    const int m0 = blockIdx.y * 64;
    float acc[1][3][4] = {};
    run_pipeline<2>(smem, g_outshi, g_outslo,
        [&](int m) { return m0 + m; },
        [&](int row) {
            size_t n = (size_t)(n0 + row) * KP;
            return BPtr{ g_dechi + n, g_declo + n };
        }, acc);

    const int lane = threadIdx.x & 31;
    const int mw = (threadIdx.x >> 5) & 3, ng = threadIdx.x >> 7;
    const int g = lane >> 2, tq = lane & 3;
#pragma unroll
    for (int r = 0; r < 2; r++) {
        const int m = m0 + 16 * mw + g + 8 * r;
        const int n = n0 + ng * 8 + 2 * tq;
        float2 db = *(const float2*)&dec_b[n];
        *(float2*)&out[(size_t)m * Vv + n] =
            make_float2(ASUM(0, 2 * r) + db.x, ASUM(0, 2 * r + 1) + db.y);
    }
}

} // namespace

// ---------------------------------------------------------------------------
extern "C" void kernel_launch(void* const* d_in, const int* in_sizes, int n_in,
                              void* d_out, int out_size)
{
    (void)in_sizes; (void)n_in; (void)out_size;

    const int*   inputs = (const int*)  d_in[0];
    const float* hidden = (const float*)d_in[1];
    const float* emb    = (const float*)d_in[2];
    const float* w_xh   = (const float*)d_in[3];
    const float* b_xh   = (const float*)d_in[4];
    const float* w_xc   = (const float*)d_in[5];
    const float* b_xc   = (const float*)d_in[6];
    const float* Wh     = (const float*)d_in[7];
    const float* Wc     = (const float*)d_in[8];
    const float* dec_w  = (const float*)d_in[9];
    const float* dec_b  = (const float*)d_in[10];
    float* out = (float*)d_out;

    cudaFuncSetAttribute(precomp_mma, cudaFuncAttributeMaxDynamicSharedMemorySize, SMEM_NB2);
    cudaFuncSetAttribute(cell0_mma,   cudaFuncAttributeMaxDynamicSharedMemorySize, SMEM_NB2);
    cudaFuncSetAttribute(level_mma,   cudaFuncAttributeMaxDynamicSharedMemorySize, SMEM_NB2);
    cudaFuncSetAttribute(last_mma,    cudaFuncAttributeMaxDynamicSharedMemorySize, SMEM_NB4);
    cudaFuncSetAttribute(decoder_mma, cudaFuncAttributeMaxDynamicSharedMemorySize, SMEM_NB2);

    // acts: 0=relu, 1=tanh, 2=sigmoid, 3=identity; split=1 if child is a parent
    const LevelDesc LV1 = {{ {0, 1, 0, 0, 1},  {0, 6, 1, 1, 1},  {0, 0, 0, 3, 0} }};
    const LevelDesc LV2 = {{ {1, 2, 2, 0, 1},  {1, 8, 3, 2, 0},  {6, 7, 10, 1, 0} }};
    const LevelDesc LV3 = {{ {2, 3, 4, 1, 1},  {2, 9, 5, 0, 0},  {0, 0, 0, 3, 0} }};
    const LevelDesc LV4 = {{ {3, 4, 6, 3, 1},  {3, 10, 7, 1, 0}, {0, 0, 0, 3, 0} }};

    prep_split<<<(PREP_UNITS + 255) / 256, 256>>>(Wh, Wc, dec_w, emb, hidden, w_xh, w_xc);
    precomp_mma<<<dim3(125, 64), 256, SMEM_NB2>>>(inputs, b_xh, b_xc);

    for (int t = 0; t < Tt; ++t) {
        cell0_mma<<<125, 256, SMEM_NB2>>>(hidden, t);
        level_mma<<<dim3(125, 2), 256, SMEM_NB2>>>(LV1);
        level_mma<<<dim3(125, 3), 256, SMEM_NB2>>>(LV2);
        level_mma<<<dim3(125, 2), 256, SMEM_NB2>>>(LV3);
        level_mma<<<dim3(125, 2), 256, SMEM_NB2>>>(LV4);
        last_mma<<<125, 256, SMEM_NB4>>>(t);
    }

    decoder_mma<<<dim3(625, 64), 256, SMEM_NB2>>>(dec_b, out);
}

// round 8
// speedup vs baseline: 1.0465x; 1.0032x over previous
#include <cuda_runtime.h>
#include <cuda_bf16.h>

// ---------------------------------------------------------------------------
// ENAS RNN — round 7: 8-warp CTAs with warp-level n-split over shared smem
// stages, prefetch issued before compute, S=6. bf16 3-term split, fp32 accum.
// ---------------------------------------------------------------------------

namespace {

typedef unsigned int u32;
typedef __nv_bfloat16 bf16;

constexpr int Hd = 1000;
constexpr int Bb = 64;
constexpr int Tt = 64;
constexpr int Vv = 10000;

constexpr int KP = 1024;          // padded K pitch (elements)
constexpr int S = 6;              // pipeline stages
constexpr int KC = 32;            // k per chunk
constexpr int NCHUNK = KP / KC;   // 32

// ---------------- static device storage (zero-initialized at load) ---------
__device__ bf16 g_Whhi[11 * 1000 * KP], g_Whlo[11 * 1000 * KP];
__device__ bf16 g_Wchi[11 * 1000 * KP], g_Wclo[11 * 1000 * KP];
__device__ bf16 g_dechi[10000 * KP], g_declo[10000 * KP];
__device__ bf16 g_embhi[10000 * KP], g_emblo[10000 * KP];
__device__ bf16 g_wxhe_hi[1000 * KP], g_wxhe_lo[1000 * KP];
__device__ bf16 g_wxhh_hi[1000 * KP], g_wxhh_lo[1000 * KP];
__device__ bf16 g_wxce_hi[1000 * KP], g_wxce_lo[1000 * KP];
__device__ bf16 g_wxch_hi[1000 * KP], g_wxch_lo[1000 * KP];

__device__ float g_h[12][Bb * Hd];
__device__ bf16  g_hhi[12][Bb * KP];
__device__ bf16  g_hlo[12][Bb * KP];
__device__ float g_c0[Bb * Hd];
__device__ float g_Ph[Tt * Bb * Hd];
__device__ float g_Pc[Tt * Bb * Hd];
__device__ bf16  g_outshi[Tt * Bb * KP];
__device__ bf16  g_outslo[Tt * Bb * KP];

// ---------------- helpers ---------------------------------------------------
__device__ __forceinline__ float sigmf(float x) { return 1.0f / (1.0f + expf(-x)); }

__device__ __forceinline__ float applyAct(int a, float v) {
    switch (a) {
        case 0: return fmaxf(v, 0.0f);
        case 1: return tanhf(v);
        case 2: return sigmf(v);
        default: return v;
    }
}

__device__ __forceinline__ void split1(float x, bf16& h, bf16& l) {
    h = __float2bfloat16(x);
    l = __float2bfloat16(x - __bfloat162float(h));
}
__device__ __forceinline__ u32 b2u(bf16 a, bf16 b) {
    return (u32)__bfloat16_as_ushort(a) | ((u32)__bfloat16_as_ushort(b) << 16);
}

__device__ __forceinline__ void mma16816(float (&d)[4], const u32 (&a)[4], u32 b0, u32 b1) {
    asm volatile(
        "mma.sync.aligned.m16n8k16.row.col.f32.bf16.bf16.f32 "
        "{%0,%1,%2,%3}, {%4,%5,%6,%7}, {%8,%9}, {%0,%1,%2,%3};"
        : "+f"(d[0]), "+f"(d[1]), "+f"(d[2]), "+f"(d[3])
        : "r"(a[0]), "r"(a[1]), "r"(a[2]), "r"(a[3]), "r"(b0), "r"(b1));
}
__device__ __forceinline__ void ldmA(u32 a, u32 (&r)[4]) {
    asm volatile("ldmatrix.sync.aligned.m8n8.x4.shared.b16 {%0,%1,%2,%3}, [%4];"
                 : "=r"(r[0]), "=r"(r[1]), "=r"(r[2]), "=r"(r[3]) : "r"(a));
}
__device__ __forceinline__ void ldmB(u32 a, u32& b0, u32& b1) {
    asm volatile("ldmatrix.sync.aligned.m8n8.x2.shared.b16 {%0,%1}, [%2];"
                 : "=r"(b0), "=r"(b1) : "r"(a));
}
__device__ __forceinline__ void cpa16(u32 dst, const void* src) {
    asm volatile("cp.async.cg.shared.global [%0], [%1], 16;" :: "r"(dst), "l"(src));
}
__device__ __forceinline__ void cp_commit() { asm volatile("cp.async.commit_group;"); }

struct BPtr { const bf16* hi; const bf16* lo; };
struct EdgeDesc { int parent; int child; int w; int act; int split; };
struct LevelDesc { EdgeDesc e[3]; };

// ---------------------------------------------------------------------------
// 8-warp pipelined GEMM mainloop. A: 64 x KP bf16 hi/lo (row via arow).
// B: NB groups of 8 rows. Warps: mw = warp&3 owns m [16mw,16mw+16);
// ng = warp>>2 owns B-groups [ng*NB/2, (ng+1)*NB/2).
// acc[jj][t]: own group jj, split-term t. D = Ahi*Bhi + Ahi*Blo + Alo*Bhi.
// Commit-count invariant: entering iter ch, committed = ch + (S-1); the
// prefetch for ch+S-1 is issued BEFORE compute (stage (ch-1)%S is free after
// the top barrier), maximizing load lead time.
// ---------------------------------------------------------------------------
template <int NB, class AROW, class BSRC>
__device__ __forceinline__ void run_pipeline(
    char* smem, const bf16* __restrict__ Ah, const bf16* __restrict__ Al,
    AROW arow, BSRC bsrc, float (&acc)[NB / 2][3][4])
{
    constexpr int NGRP = NB / 2;
    constexpr int AHI = 0, ALO = 5120, BHI = 10240, BLO = 10240 + NB * 640;
    constexpr int SS = 10240 + 2 * NB * 640;

    const int tid = threadIdx.x;
    const u32 sbase = (u32)__cvta_generic_to_shared(smem);

    // A: one 16B vector per precision per thread (256 vecs per precision).
    const size_t aoff = (size_t)arow(tid >> 2) * KP + (tid & 3) * 8;
    const u32 adst = (u32)((tid >> 2) * 80 + (tid & 3) * 16);

    // B: NB*64 vectors total (hi then lo), one per thread where valid.
    const bool bval = tid < NB * 64;
    const int e = bval ? tid : 0;
    const bool blo = e >= NB * 32;
    const int f = blo ? e - NB * 32 : e;
    BPtr p = bsrc(f >> 2);
    const bf16* bp = (blo ? p.lo : p.hi) + (f & 3) * 8;
    const u32 bd = (u32)((blo ? BLO : BHI) + (f >> 2) * 80 + (f & 3) * 16);

    auto issue = [&](int ch) {
        const u32 st = sbase + (u32)((ch % S) * SS);
        const int k0 = ch * KC;
        cpa16(st + AHI + adst, Ah + aoff + k0);
        cpa16(st + ALO + adst, Al + aoff + k0);
        if (bval) cpa16(st + bd, bp + k0);
        cp_commit();
    };

    const int lane = tid & 31;
    const int mw = (tid >> 5) & 3, ng = tid >> 7;
    const int qq = lane >> 3, rr = lane & 7;
    const u32 aAddr = (u32)((16 * mw + ((qq & 1) ? 8 : 0) + rr) * 80 + ((qq & 2) ? 16 : 0));
    const u32 bAddr = (u32)(rr * 80 + ((qq & 1) ? 16 : 0));

#pragma unroll
    for (int c = 0; c < S - 1; ++c) issue(c);

    for (int ch = 0; ch < NCHUNK; ++ch) {
        asm volatile("cp.async.wait_group %0;" :: "n"(S - 2));
        __syncthreads();
        if (ch + S - 1 < NCHUNK) issue(ch + S - 1);
        else cp_commit();                 // keep commit count = ch + S
        const u32 st = sbase + (u32)((ch % S) * SS);
#pragma unroll
        for (int k16 = 0; k16 < KC / 16; k16++) {
            const u32 ko = (u32)(k16 * 32);  // bytes
            u32 ah[4], al[4];
            ldmA(st + AHI + aAddr + ko, ah);
            ldmA(st + ALO + aAddr + ko, al);
#pragma unroll
            for (int jj = 0; jj < NGRP; jj++) {
                const int j = ng * NGRP + jj;
                u32 bh0, bh1, bl0, bl1;
                ldmB(st + BHI + (u32)(j * 640) + bAddr + ko, bh0, bh1);
                ldmB(st + BLO + (u32)(j * 640) + bAddr + ko, bl0, bl1);
                mma16816(acc[jj][0], ah, bh0, bh1);
                mma16816(acc[jj][1], ah, bl0, bl1);
                mma16816(acc[jj][2], al, bh0, bh1);
            }
        }
    }
    __syncthreads();   // smem stages now dead; reusable for epilogue exchange
}

constexpr int SMEM_NB2 = (10240 + 2 * 2 * 640) * S;   // 76800
constexpr int SMEM_NB4 = (10240 + 2 * 4 * 640) * S;   // 92160

// Store a warp's 3-term-summed acc group into exchange smem: ex[jj][m 0..63][n 0..7]
__device__ __forceinline__ void ex_store(float* ex, int jj, const float (&a)[3][4],
                                         int mw, int lane) {
    const int g = lane >> 2, tq = lane & 3;
#pragma unroll
    for (int r = 0; r < 2; r++) {
        float2 v = make_float2(a[0][2 * r] + a[1][2 * r] + a[2][2 * r],
                               a[0][2 * r + 1] + a[1][2 * r + 1] + a[2][2 * r + 1]);
        *(float2*)&ex[jj * 512 + (16 * mw + g + 8 * r) * 8 + 2 * tq] = v;
    }
}

#define ASUM(jj, i) (acc[jj][0][i] + acc[jj][1][i] + acc[jj][2][i])

// ---------------------------------------------------------------------------
// prep: split all static fp32 operands into bf16 hi/lo with padded pitch.
// ---------------------------------------------------------------------------
constexpr int U_W = 11000 * 250;
constexpr int U_DEC = 10000 * 250;
constexpr int U_EMB = 10000 * 250;
constexpr int U_HID = 64 * 250;
constexpr int U_WX = 1000 * 250;
constexpr int P0 = U_W;
constexpr int P1 = P0 + U_W;
constexpr int P2 = P1 + U_DEC;
constexpr int P3 = P2 + U_EMB;
constexpr int P4 = P3 + U_HID;
constexpr int P5 = P4 + U_WX;
constexpr int P6 = P5 + U_WX;
constexpr int PREP_UNITS = P6;

__device__ __forceinline__ void split4_store(float4 v, bf16* hi, bf16* lo, size_t o) {
    bf16 h0, l0, h1, l1, h2, l2, h3, l3;
    split1(v.x, h0, l0); split1(v.y, h1, l1); split1(v.z, h2, l2); split1(v.w, h3, l3);
    *(uint2*)&hi[o] = make_uint2(b2u(h0, h1), b2u(h2, h3));
    *(uint2*)&lo[o] = make_uint2(b2u(l0, l1), b2u(l2, l3));
}

__global__ __launch_bounds__(256) void prep_split(
    const float* __restrict__ Wh, const float* __restrict__ Wc,
    const float* __restrict__ dec_w, const float* __restrict__ emb,
    const float* __restrict__ hidden,
    const float* __restrict__ w_xh, const float* __restrict__ w_xc)
{
    int i = blockIdx.x * 256 + threadIdx.x;
    if (i >= PREP_UNITS) return;
    if (i < P0) {
        int row = i / 250, col = (i % 250) * 4;
        split4_store(*(const float4*)(Wh + (size_t)row * 1000 + col),
                     g_Whhi, g_Whlo, (size_t)row * KP + col);
    } else if (i < P1) {
        int j = i - P0; int row = j / 250, col = (j % 250) * 4;
        split4_store(*(const float4*)(Wc + (size_t)row * 1000 + col),
                     g_Wchi, g_Wclo, (size_t)row * KP + col);
    } else if (i < P2) {
        int j = i - P1; int row = j / 250, col = (j % 250) * 4;
        split4_store(*(const float4*)(dec_w + (size_t)row * 1000 + col),
                     g_dechi, g_declo, (size_t)row * KP + col);
    } else if (i < P3) {
        int j = i - P2; int row = j / 250, col = (j % 250) * 4;
        split4_store(*(const float4*)(emb + (size_t)row * 1000 + col),
                     g_embhi, g_emblo, (size_t)row * KP + col);
    } else if (i < P4) {
        int j = i - P3; int row = j / 250, col = (j % 250) * 4;
        split4_store(*(const float4*)(hidden + (size_t)row * 1000 + col),
                     g_hhi[11], g_hlo[11], (size_t)row * KP + col);
    } else if (i < P5) {
        int j = i - P4; int row = j / 250, col = (j % 250) * 4;
        split4_store(*(const float4*)(w_xh + (size_t)row * 2000 + col),
                     g_wxhe_hi, g_wxhe_lo, (size_t)row * KP + col);
        split4_store(*(const float4*)(w_xh + (size_t)row * 2000 + 1000 + col),
                     g_wxhh_hi, g_wxhh_lo, (size_t)row * KP + col);
    } else {
        int j = i - P5; int row = j / 250, col = (j % 250) * 4;
        split4_store(*(const float4*)(w_xc + (size_t)row * 2000 + col),
                     g_wxce_hi, g_wxce_lo, (size_t)row * KP + col);
        split4_store(*(const float4*)(w_xc + (size_t)row * 2000 + 1000 + col),
                     g_wxch_hi, g_wxch_lo, (size_t)row * KP + col);
    }
}

// ---------------------------------------------------------------------------
// precomp: P{h,c} = gather(emb) @ w_x{h,c}_embpart^T + bias. grid (125, 64).
// Groups: 0 -> Ph (warps 0-3 write), 1 -> Pc (warps 4-7 write). No exchange.
// ---------------------------------------------------------------------------
__global__ __launch_bounds__(256) void precomp_mma(
    const int* __restrict__ inputs,
    const float* __restrict__ b_xh, const float* __restrict__ b_xc)
{
    extern __shared__ char smem[];
    __shared__ int toks[64];
    const int m0 = blockIdx.y * 64;
    if (threadIdx.x < 64) toks[threadIdx.x] = inputs[m0 + threadIdx.x];
    __syncthreads();

    const int n0 = blockIdx.x * 8;
    float acc[1][3][4] = {};
    run_pipeline<2>(smem, g_embhi, g_emblo,
        [&](int m) { return toks[m]; },
        [&](int row) {
            size_t n = (size_t)(n0 + (row & 7)) * KP;
            return (row < 8) ? BPtr{ g_wxhe_hi + n, g_wxhe_lo + n }
                             : BPtr{ g_wxce_hi + n, g_wxce_lo + n };
        }, acc);

    const int lane = threadIdx.x & 31;
    const int mw = (threadIdx.x >> 5) & 3, ng = threadIdx.x >> 7;
    const int g = lane >> 2, tq = lane & 3;
    const float* bias = ng ? b_xc : b_xh;
    float* dst = ng ? g_Pc : g_Ph;
#pragma unroll
    for (int r = 0; r < 2; r++) {
        const int m = m0 + 16 * mw + g + 8 * r;
        const int n = n0 + 2 * tq;
        float2 bb = *(const float2*)&bias[n];
        *(float2*)&dst[(size_t)m * Hd + n] =
            make_float2(ASUM(0, 2 * r) + bb.x, ASUM(0, 2 * r + 1) + bb.y);
    }
}

// ---------------------------------------------------------------------------
// cell0: dual GEMM vs h_prev (K=1000) + precomputed emb part. grid 125.
// ---------------------------------------------------------------------------
__global__ __launch_bounds__(256) void cell0_mma(const float* __restrict__ hidden, int t)
{
    extern __shared__ char smem[];
    const float* __restrict__ hprev = (t == 0) ? hidden : g_h[11];
    const int n0 = blockIdx.x * 8;
    float acc[1][3][4] = {};
    run_pipeline<2>(smem, g_hhi[11], g_hlo[11],
        [](int m) { return m; },
        [&](int row) {
            size_t n = (size_t)(n0 + (row & 7)) * KP;
            return (row < 8) ? BPtr{ g_wxhh_hi + n, g_wxhh_lo + n }
                             : BPtr{ g_wxch_hi + n, g_wxch_lo + n };
        }, acc);

    float* ex = (float*)smem;
    const int lane = threadIdx.x & 31;
    const int mw = (threadIdx.x >> 5) & 3, ng = threadIdx.x >> 7;
    const int g = lane >> 2, tq = lane & 3;
    if (ng == 1) ex_store(ex, 0, acc[0], mw, lane);   // Wc sums
    __syncthreads();
    if (ng == 0) {
#pragma unroll
        for (int r = 0; r < 2; r++) {
            const int m = 16 * mw + g + 8 * r;
            const int n = n0 + 2 * tq;
            const int idx = m * Hd + n;
            const size_t pidx = (size_t)(t * Bb + m) * Hd + n;
            float2 sc = *(const float2*)&ex[(16 * mw + g + 8 * r) * 8 + 2 * tq];
            float2 ph = *(const float2*)&g_Ph[pidx];
            float2 pc = *(const float2*)&g_Pc[pidx];
            float2 hp = *(const float2*)&hprev[idx];
            float c0a = sigmf(sc.x + pc.x);
            float c0b = sigmf(sc.y + pc.y);
            float h0a = c0a * tanhf(ASUM(0, 2 * r) + ph.x) + (1.0f - c0a) * hp.x;
            float h0b = c0b * tanhf(ASUM(0, 2 * r + 1) + ph.y) + (1.0f - c0b) * hp.y;
            *(float2*)&g_c0[idx] = make_float2(c0a, c0b);
            *(float2*)&g_h[0][idx] = make_float2(h0a, h0b);
            bf16 ha, la, hb, lb;
            split1(h0a, ha, la); split1(h0b, hb, lb);
            const size_t sidx = (size_t)m * KP + n;
            *(u32*)&g_hhi[0][sidx] = b2u(ha, hb);
            *(u32*)&g_hlo[0][sidx] = b2u(la, lb);
        }
    }
}

// ---------------------------------------------------------------------------
// Generic DAG level. grid = (125, n_edges).
// ---------------------------------------------------------------------------
__global__ __launch_bounds__(256) void level_mma(LevelDesc L)
{
    extern __shared__ char smem[];
    const EdgeDesc ed = L.e[blockIdx.y];
    const float* __restrict__ hin = g_h[ed.parent];
    float* __restrict__ hout = g_h[ed.child];
    const bf16* whh = g_Whhi + (size_t)ed.w * 1000 * KP;
    const bf16* whl = g_Whlo + (size_t)ed.w * 1000 * KP;
    const bf16* wch = g_Wchi + (size_t)ed.w * 1000 * KP;
    const bf16* wcl = g_Wclo + (size_t)ed.w * 1000 * KP;
    const int n0 = blockIdx.x * 8;

    float acc[1][3][4] = {};
    run_pipeline<2>(smem, g_hhi[ed.parent], g_hlo[ed.parent],
        [](int m) { return m; },
        [&](int row) {
            size_t n = (size_t)(n0 + (row & 7)) * KP;
            return (row < 8) ? BPtr{ whh + n, whl + n } : BPtr{ wch + n, wcl + n };
        }, acc);

    float* ex = (float*)smem;
    const int lane = threadIdx.x & 31;
    const int mw = (threadIdx.x >> 5) & 3, ng = threadIdx.x >> 7;
    const int g = lane >> 2, tq = lane & 3;
    if (ng == 1) ex_store(ex, 0, acc[0], mw, lane);   // Wc sums
    __syncthreads();
    if (ng == 0) {
#pragma unroll
        for (int r = 0; r < 2; r++) {
            const int m = 16 * mw + g + 8 * r;
            const int n = n0 + 2 * tq;
            const int idx = m * Hd + n;
            float2 sc = *(const float2*)&ex[(16 * mw + g + 8 * r) * 8 + 2 * tq];
            float2 hi2 = *(const float2*)&hin[idx];
            float2 c02 = *(const float2*)&g_c0[idx];
            float oa = sigmf(sc.x) * applyAct(ed.act, ASUM(0, 2 * r))
                       + (1.0f - c02.x) * hi2.x;
            float ob = sigmf(sc.y) * applyAct(ed.act, ASUM(0, 2 * r + 1))
                       + (1.0f - c02.y) * hi2.y;
            *(float2*)&hout[idx] = make_float2(oa, ob);
            if (ed.split) {
                bf16 ha, la, hb, lb;
                split1(oa, ha, la); split1(ob, hb, lb);
                const size_t sidx = (size_t)m * KP + n;
                *(u32*)&g_hhi[ed.child][sidx] = b2u(ha, hb);
                *(u32*)&g_hlo[ed.child][sidx] = b2u(la, lb);
            }
        }
    }
}

// ---------------------------------------------------------------------------
// Last level fused: edges 8 (4->5, relu) and 9 (4->11, sigmoid) + leaf mean.
// NB=4 groups: [Wh8, Wc8 | Wh9, Wc9]; warps 0-3 own h5 pair, 4-7 own h11 pair.
// grid 125.
// ---------------------------------------------------------------------------
__global__ __launch_bounds__(256) void last_mma(int t)
{
    extern __shared__ char smem[];
    const int n0 = blockIdx.x * 8;
    const bf16* base_hi[4] = { g_Whhi + (size_t)8 * 1000 * KP, g_Wchi + (size_t)8 * 1000 * KP,
                               g_Whhi + (size_t)9 * 1000 * KP, g_Wchi + (size_t)9 * 1000 * KP };
    const bf16* base_lo[4] = { g_Whlo + (size_t)8 * 1000 * KP, g_Wclo + (size_t)8 * 1000 * KP,
                               g_Whlo + (size_t)9 * 1000 * KP, g_Wclo + (size_t)9 * 1000 * KP };

    float acc[2][3][4] = {};
    run_pipeline<4>(smem, g_hhi[4], g_hlo[4],
        [](int m) { return m; },
        [&](int row) {
            int mat = row >> 3;
            size_t n = (size_t)(n0 + (row & 7)) * KP;
            return BPtr{ base_hi[mat] + n, base_lo[mat] + n };
        }, acc);

    float* ex = (float*)smem;
    const int lane = threadIdx.x & 31;
    const int mw = (threadIdx.x >> 5) & 3, ng = threadIdx.x >> 7;
    const int g = lane >> 2, tq = lane & 3;
    if (ng == 1) {                         // Wh9, Wc9 sums
        ex_store(ex, 0, acc[0], mw, lane);
        ex_store(ex, 1, acc[1], mw, lane);
    }
    __syncthreads();
    if (ng == 0) {
#pragma unroll
        for (int r = 0; r < 2; r++) {
            const int m = 16 * mw + g + 8 * r;
            const int n = n0 + 2 * tq;
            const int idx = m * Hd + n;
            const int eo = (16 * mw + g + 8 * r) * 8 + 2 * tq;
            float2 s9h = *(const float2*)&ex[eo];          // Wh9
            float2 s9c = *(const float2*)&ex[512 + eo];    // Wc9
            float2 h4v = *(const float2*)&g_h[4][idx];
            float2 c02 = *(const float2*)&g_c0[idx];
            float oma = 1.0f - c02.x, omb = 1.0f - c02.y;
            float h5a  = sigmf(ASUM(1, 2 * r))     * fmaxf(ASUM(0, 2 * r), 0.0f)     + oma * h4v.x;
            float h5b  = sigmf(ASUM(1, 2 * r + 1)) * fmaxf(ASUM(0, 2 * r + 1), 0.0f) + omb * h4v.y;
            float h11a = sigmf(s9c.x) * sigmf(s9h.x) + oma * h4v.x;
            float h11b = sigmf(s9c.y) * sigmf(s9h.y) + omb * h4v.y;
            *(float2*)&g_h[11][idx] = make_float2(h11a, h11b);
            bf16 ha, la, hb, lb;
            split1(h11a, ha, la); split1(h11b, hb, lb);
            const size_t sidx = (size_t)m * KP + n;
            *(u32*)&g_hhi[11][sidx] = b2u(ha, hb);
            *(u32*)&g_hlo[11][sidx] = b2u(la, lb);

            float2 h7 = *(const float2*)&g_h[7][idx];
            float2 h8 = *(const float2*)&g_h[8][idx];
            float2 h9 = *(const float2*)&g_h[9][idx];
            float2 hA = *(const float2*)&g_h[10][idx];
            float oa = (h5a + h11a + h7.x + h8.x + h9.x + hA.x) * (1.0f / 6.0f);
            float ob = (h5b + h11b + h7.y + h8.y + h9.y + hA.y) * (1.0f / 6.0f);
            split1(oa, ha, la); split1(ob, hb, lb);
            const size_t oidx = (size_t)(t * Bb + m) * KP + n;
            *(u32*)&g_outshi[oidx] = b2u(ha, hb);
            *(u32*)&g_outslo[oidx] = b2u(la, lb);
        }
    }
}

// ---------------------------------------------------------------------------
// Decoder: out[m][v] = outs[m] . dec_w[v] + dec_b[v]; grid (625, 64).
// Groups are disjoint n-ranges; each warp writes its own. No exchange.
// ---------------------------------------------------------------------------
__global__ __launch_bounds__(256) void decoder_mma(
    const float* __restrict__ dec_b, float* __restrict__ out)
{
    extern __shared__ char smem[];
    const int n0 = blockIdx.x * 16;
    const int m0 = blockIdx.y * 64;
    float acc[1][3][4] = {};
    run_pipeline<2>(smem, g_outshi, g_outslo,
        [&](int m) { return m0 + m; },
        [&](int row) {
            size_t n = (size_t)(n0 + row) * KP;
            return BPtr{ g_dechi + n, g_declo + n };
        }, acc);

    const int lane = threadIdx.x & 31;
    const int mw = (threadIdx.x >> 5) & 3, ng = threadIdx.x >> 7;
    const int g = lane >> 2, tq = lane & 3;
#pragma unroll
    for (int r = 0; r < 2; r++) {
        const int m = m0 + 16 * mw + g + 8 * r;
        const int n = n0 + ng * 8 + 2 * tq;
        float2 db = *(const float2*)&dec_b[n];
        *(float2*)&out[(size_t)m * Vv + n] =
            make_float2(ASUM(0, 2 * r) + db.x, ASUM(0, 2 * r + 1) + db.y);
    }
}

} // namespace

// ---------------------------------------------------------------------------
extern "C" void kernel_launch(void* const* d_in, const int* in_sizes, int n_in,
                              void* d_out, int out_size)
{
    (void)in_sizes; (void)n_in; (void)out_size;

    const int*   inputs = (const int*)  d_in[0];
    const float* hidden = (const float*)d_in[1];
    const float* emb    = (const float*)d_in[2];
    const float* w_xh   = (const float*)d_in[3];
    const float* b_xh   = (const float*)d_in[4];
    const float* w_xc   = (const float*)d_in[5];
    const float* b_xc   = (const float*)d_in[6];
    const float* Wh     = (const float*)d_in[7];
    const float* Wc     = (const float*)d_in[8];
    const float* dec_w  = (const float*)d_in[9];
    const float* dec_b  = (const float*)d_in[10];
    float* out = (float*)d_out;

    cudaFuncSetAttribute(precomp_mma, cudaFuncAttributeMaxDynamicSharedMemorySize, SMEM_NB2);
    cudaFuncSetAttribute(cell0_mma,   cudaFuncAttributeMaxDynamicSharedMemorySize, SMEM_NB2);
    cudaFuncSetAttribute(level_mma,   cudaFuncAttributeMaxDynamicSharedMemorySize, SMEM_NB2);
    cudaFuncSetAttribute(last_mma,    cudaFuncAttributeMaxDynamicSharedMemorySize, SMEM_NB4);
    cudaFuncSetAttribute(decoder_mma, cudaFuncAttributeMaxDynamicSharedMemorySize, SMEM_NB2);

    // acts: 0=relu, 1=tanh, 2=sigmoid, 3=identity; split=1 if child is a parent
    const LevelDesc LV1 = {{ {0, 1, 0, 0, 1},  {0, 6, 1, 1, 1},  {0, 0, 0, 3, 0} }};
    const LevelDesc LV2 = {{ {1, 2, 2, 0, 1},  {1, 8, 3, 2, 0},  {6, 7, 10, 1, 0} }};
    const LevelDesc LV3 = {{ {2, 3, 4, 1, 1},  {2, 9, 5, 0, 0},  {0, 0, 0, 3, 0} }};
    const LevelDesc LV4 = {{ {3, 4, 6, 3, 1},  {3, 10, 7, 1, 0}, {0, 0, 0, 3, 0} }};

    prep_split<<<(PREP_UNITS + 255) / 256, 256>>>(Wh, Wc, dec_w, emb, hidden, w_xh, w_xc);
    precomp_mma<<<dim3(125, 64), 256, SMEM_NB2>>>(inputs, b_xh, b_xc);

    for (int t = 0; t < Tt; ++t) {
        cell0_mma<<<125, 256, SMEM_NB2>>>(hidden, t);
        level_mma<<<dim3(125, 2), 256, SMEM_NB2>>>(LV1);
        level_mma<<<dim3(125, 3), 256, SMEM_NB2>>>(LV2);
        level_mma<<<dim3(125, 2), 256, SMEM_NB2>>>(LV3);
        level_mma<<<dim3(125, 2), 256, SMEM_NB2>>>(LV4);
        last_mma<<<125, 256, SMEM_NB4>>>(t);
    }

    decoder_mma<<<dim3(625, 64), 256, SMEM_NB2>>>(dec_b, out);
}